// round 1
// baseline (speedup 1.0000x reference)
#include <cuda_runtime.h>
#include <math.h>

#define S_DIM 128
#define R_DIM 256
#define CS 256
#define CH 32
#define CZ 128
#define MDIM 8192           // R_DIM * CH
#define NROWS 32768         // S_DIM * R_DIM
#define LN_EPS 1e-5f
#define MASK_EPS 1e-3f

// Scratch (static __device__ arrays — no cudaMalloc allowed)
__device__ float g_a[S_DIM * MDIM];                 // [s][i*32+h], 4 MB
__device__ float g_b[S_DIM * MDIM];                 // [s][j*32+k], 4 MB
__device__ float g_outer[(size_t)65536 * 1024];     // [i][j][h][k], 268 MB

// ---------------------------------------------------------------------------
// Kernel 1: LayerNorm + dual projection (+bias, *mask) -> g_a, g_b
// 16 rows per block of 256 threads. Weights read via L1 (64 KB, fully resident).
// ---------------------------------------------------------------------------
__global__ __launch_bounds__(256) void k_proj(
    const float* __restrict__ m, const float* __restrict__ mask,
    const float* __restrict__ lnw, const float* __restrict__ lnb,
    const float* __restrict__ w1, const float* __restrict__ b1,
    const float* __restrict__ w2, const float* __restrict__ b2)
{
    __shared__ float mhs[16][CS];     // 16 KB
    __shared__ float lnws[CS], lnbs[CS];

    int tid  = threadIdx.x;
    int lane = tid & 31;
    int wid  = tid >> 5;

    lnws[tid] = lnw[tid];
    lnbs[tid] = lnb[tid];
    __syncthreads();

    int row0 = blockIdx.x * 16;

    // LayerNorm: each warp handles 2 rows (8 warps x 2 = 16 rows)
    #pragma unroll
    for (int rr = 0; rr < 2; rr++) {
        int rl  = wid * 2 + rr;
        int row = row0 + rl;
        const float4* mrow = (const float4*)(m + (size_t)row * CS);
        float4 v0 = mrow[lane * 2];
        float4 v1 = mrow[lane * 2 + 1];
        float s1 = v0.x + v0.y + v0.z + v0.w + v1.x + v1.y + v1.z + v1.w;
        float s2 = v0.x*v0.x + v0.y*v0.y + v0.z*v0.z + v0.w*v0.w
                 + v1.x*v1.x + v1.y*v1.y + v1.z*v1.z + v1.w*v1.w;
        #pragma unroll
        for (int off = 16; off; off >>= 1) {
            s1 += __shfl_xor_sync(0xffffffffu, s1, off);
            s2 += __shfl_xor_sync(0xffffffffu, s2, off);
        }
        float mu   = s1 * (1.0f / CS);
        float var  = s2 * (1.0f / CS) - mu * mu;
        float rstd = rsqrtf(var + LN_EPS);
        int c0 = lane * 8;
        float t[8] = {v0.x, v0.y, v0.z, v0.w, v1.x, v1.y, v1.z, v1.w};
        #pragma unroll
        for (int q = 0; q < 8; q++) {
            int c = c0 + q;
            mhs[rl][c] = (t[q] - mu) * rstd * lnws[c] + lnbs[c];
        }
    }
    __syncthreads();

    // Projection: 256 threads = 4 row-groups x 64 outputs (o<32 -> w1/a, else w2/b)
    int o  = tid & 63;
    int rg = tid >> 6;                 // 0..3, rows rg*4 .. rg*4+3
    int h  = o & 31;
    const float* wp = (o < 32) ? (w1 + h) : (w2 + h);
    float acc0 = 0.f, acc1 = 0.f, acc2 = 0.f, acc3 = 0.f;
    #pragma unroll 8
    for (int c = 0; c < CS; c++) {
        float wv = __ldg(wp + c * CH);
        acc0 += mhs[rg * 4 + 0][c] * wv;
        acc1 += mhs[rg * 4 + 1][c] * wv;
        acc2 += mhs[rg * 4 + 2][c] * wv;
        acc3 += mhs[rg * 4 + 3][c] * wv;
    }
    float bias = (o < 32) ? b1[h] : b2[h];
    float* dst = (o < 32) ? g_a : g_b;
    float accs[4] = {acc0, acc1, acc2, acc3};
    #pragma unroll
    for (int jj = 0; jj < 4; jj++) {
        int row = row0 + rg * 4 + jj;
        int s = row >> 8;
        int r = row & 255;
        float val = (accs[jj] + bias) * mask[row];
        dst[(size_t)s * MDIM + r * CH + h] = val;
    }
}

// ---------------------------------------------------------------------------
// Kernel 2: outer contraction GEMM. C[m=(i,h), n=(j,k)] = sum_s A[s,m]*B[s,n]
// 128x128 block tile, K chunked by 32, 8x8 per-thread micro-tile.
// Epilogue writes to g_outer in [i][j][h][k] layout (contiguous hk per pair).
// ---------------------------------------------------------------------------
__global__ __launch_bounds__(256) void k_gemm1()
{
    __shared__ float As[32 * 128];   // 16 KB, [k][m]
    __shared__ float Bs[32 * 128];   // 16 KB, [k][n]

    int tid = threadIdx.x;
    int m0 = blockIdx.x * 128;
    int n0 = blockIdx.y * 128;
    int tx = tid & 15;
    int ty = tid >> 4;

    float acc[8][8];
    #pragma unroll
    for (int a = 0; a < 8; a++)
        #pragma unroll
        for (int b = 0; b < 8; b++) acc[a][b] = 0.f;

    for (int k0 = 0; k0 < S_DIM; k0 += 32) {
        if (k0) __syncthreads();
        // load 32x128 tiles of A and B (1024 float4 each / 256 threads)
        #pragma unroll
        for (int i4 = 0; i4 < 4; i4++) {
            int f4 = tid + i4 * 256;
            int k  = f4 >> 5;
            int q  = f4 & 31;
            *(float4*)&As[k * 128 + q * 4] =
                *(const float4*)&g_a[(size_t)(k0 + k) * MDIM + m0 + q * 4];
            *(float4*)&Bs[k * 128 + q * 4] =
                *(const float4*)&g_b[(size_t)(k0 + k) * MDIM + n0 + q * 4];
        }
        __syncthreads();

        #pragma unroll 8
        for (int k = 0; k < 32; k++) {
            float4 a0 = *(float4*)&As[k * 128 + tx * 4];
            float4 a1 = *(float4*)&As[k * 128 + 64 + tx * 4];
            float4 b0 = *(float4*)&Bs[k * 128 + ty * 4];
            float4 b1 = *(float4*)&Bs[k * 128 + 64 + ty * 4];
            float am[8] = {a0.x, a0.y, a0.z, a0.w, a1.x, a1.y, a1.z, a1.w};
            float bn[8] = {b0.x, b0.y, b0.z, b0.w, b1.x, b1.y, b1.z, b1.w};
            #pragma unroll
            for (int mi = 0; mi < 8; mi++)
                #pragma unroll
                for (int ni = 0; ni < 8; ni++)
                    acc[mi][ni] += am[mi] * bn[ni];
        }
    }

    // Epilogue: scatter into [i][j][h][k] layout, float4 along k
    #pragma unroll
    for (int mi = 0; mi < 8; mi++) {
        int mfrag = (mi < 4) ? (tx * 4 + mi) : (64 + tx * 4 + (mi - 4));
        int mm = m0 + mfrag;
        int i  = mm >> 5;
        int h  = mm & 31;
        #pragma unroll
        for (int half = 0; half < 2; half++) {
            int nn = n0 + half * 64 + ty * 4;
            int j  = nn >> 5;
            int kk = nn & 31;
            float4 v = make_float4(acc[mi][half * 4 + 0], acc[mi][half * 4 + 1],
                                   acc[mi][half * 4 + 2], acc[mi][half * 4 + 3]);
            *(float4*)&g_outer[(size_t)(i * R_DIM + j) * 1024 + h * 32 + kk] = v;
        }
    }
}

// ---------------------------------------------------------------------------
// Kernel 3: output GEMM + bias + mask-norm divide.
// out[p, z] = (sum_hk outer[p, hk] * w_out[hk, z] + b_out[z]) / (eps + norm[p])
// 64 pairs x 128 z per block, K=1024 chunked by 32.
// ---------------------------------------------------------------------------
__global__ __launch_bounds__(256) void k_gemm2(
    const float* __restrict__ mask, const float* __restrict__ w_out,
    const float* __restrict__ b_out, float* __restrict__ out)
{
    __shared__ float Ws[32 * 128];   // 16 KB, [kk][z]
    __shared__ float Asm[64 * 32];   // 8 KB,  [p][kk]
    __shared__ float norms[64];

    int tid = threadIdx.x;
    int p0  = blockIdx.x * 64;
    int i   = p0 >> 8;
    int j0  = p0 & 255;

    if (tid < 64) {
        float nacc = 0.f;
        #pragma unroll 4
        for (int s = 0; s < S_DIM; s++)
            nacc += mask[s * R_DIM + i] * mask[s * R_DIM + j0 + tid];
        norms[tid] = nacc;
    }

    int tz = tid & 31;     // z quad: z0 = tz*4
    int tp = tid >> 5;     // 8 p-groups of 8 pairs each

    float acc[8][4];
    #pragma unroll
    for (int a = 0; a < 8; a++)
        #pragma unroll
        for (int b = 0; b < 4; b++) acc[a][b] = 0.f;

    for (int kk0 = 0; kk0 < 1024; kk0 += 32) {
        __syncthreads();
        // load Asm: 64 p x 32 kk = 512 float4
        #pragma unroll
        for (int i4 = 0; i4 < 2; i4++) {
            int f4 = tid + i4 * 256;
            int pp = f4 >> 3;
            int kq = f4 & 7;
            *(float4*)&Asm[pp * 32 + kq * 4] =
                *(const float4*)&g_outer[(size_t)(p0 + pp) * 1024 + kk0 + kq * 4];
        }
        // load Ws: 32 kk x 128 z = 1024 float4
        #pragma unroll
        for (int i4 = 0; i4 < 4; i4++) {
            int f4 = tid + i4 * 256;
            int kk = f4 >> 5;
            int zq = f4 & 31;
            *(float4*)&Ws[kk * 128 + zq * 4] =
                *(const float4*)&w_out[(size_t)(kk0 + kk) * 128 + zq * 4];
        }
        __syncthreads();

        #pragma unroll 8
        for (int kk = 0; kk < 32; kk++) {
            float4 wv = *(float4*)&Ws[kk * 128 + tz * 4];
            #pragma unroll
            for (int jj = 0; jj < 8; jj++) {
                float av = Asm[(tp * 8 + jj) * 32 + kk];
                acc[jj][0] += av * wv.x;
                acc[jj][1] += av * wv.y;
                acc[jj][2] += av * wv.z;
                acc[jj][3] += av * wv.w;
            }
        }
    }

    float4 bz = *(const float4*)&b_out[tz * 4];
    #pragma unroll
    for (int jj = 0; jj < 8; jj++) {
        int pp = tp * 8 + jj;
        float inv = 1.0f / (MASK_EPS + norms[pp]);
        float4 v = make_float4((acc[jj][0] + bz.x) * inv,
                               (acc[jj][1] + bz.y) * inv,
                               (acc[jj][2] + bz.z) * inv,
                               (acc[jj][3] + bz.w) * inv);
        *(float4*)&out[(size_t)(p0 + pp) * CZ + tz * 4] = v;
    }
}

// ---------------------------------------------------------------------------
extern "C" void kernel_launch(void* const* d_in, const int* in_sizes, int n_in,
                              void* d_out, int out_size)
{
    const float* m     = (const float*)d_in[0];
    const float* mask  = (const float*)d_in[1];
    const float* lnw   = (const float*)d_in[2];
    const float* lnb   = (const float*)d_in[3];
    const float* w1    = (const float*)d_in[4];
    const float* b1    = (const float*)d_in[5];
    const float* w2    = (const float*)d_in[6];
    const float* b2    = (const float*)d_in[7];
    const float* w_out = (const float*)d_in[8];
    const float* b_out = (const float*)d_in[9];
    float* out = (float*)d_out;

    k_proj<<<NROWS / 16, 256>>>(m, mask, lnw, lnb, w1, b1, w2, b2);
    k_gemm1<<<dim3(MDIM / 128, MDIM / 128), 256>>>();
    k_gemm2<<<(R_DIM * R_DIM) / 64, 256>>>(mask, w_out, b_out, out);
}